// round 10
// baseline (speedup 1.0000x reference)
#include <cuda_runtime.h>
#include <cuda_fp16.h>

#define B_ 16
#define T_ 4096
#define C_ 512
#define K_ 3
#define L_ 64
#define G_ (T_ / L_)            // 64 chunks
#define CH_ 256                 // channels per block
#define NH_ (C_ / CH_)          // 2 halves
#define NCHAIN_ (B_ * NH_)      // 32 carry chains
#define NBLK_ (G_ * NCHAIN_)    // 2048 blocks
#define NTHR_ 128               // 128 threads, 2 channels each
#define EPSV 1e-4f
#define SMEM_BYTES (L_ * NTHR_ * sizeof(__half2))   // 32 KB

typedef unsigned long long u64;

// ---- packed fp32x2 helpers (sm_100+: fma/mul/add.rn.f32x2) ----
__device__ __forceinline__ u64 pk2(float lo, float hi) {
    u64 r; asm("mov.b64 %0,{%1,%2};" : "=l"(r) : "f"(lo), "f"(hi)); return r;
}
__device__ __forceinline__ float2 up2(u64 v) {
    float2 r; asm("mov.b64 {%0,%1},%2;" : "=f"(r.x), "=f"(r.y) : "l"(v)); return r;
}
__device__ __forceinline__ u64 fma2_(u64 a, u64 b, u64 c) {
    u64 d; asm("fma.rn.f32x2 %0,%1,%2,%3;" : "=l"(d) : "l"(a), "l"(b), "l"(c)); return d;
}
__device__ __forceinline__ u64 mul2_(u64 a, u64 b) {
    u64 d; asm("mul.rn.f32x2 %0,%1,%2;" : "=l"(d) : "l"(a), "l"(b)); return d;
}
__device__ __forceinline__ u64 add2_(u64 a, u64 b) {
    u64 d; asm("add.rn.f32x2 %0,%1,%2;" : "=l"(d) : "l"(a), "l"(b)); return d;
}

// Lookback scratch (no allocations -> __device__ globals, zero-init).
__device__ float g_E[NBLK_ * K_ * CH_];  // chunk-local end states (zero-init recurrence)
__device__ float g_V[NBLK_ * K_ * CH_];  // inclusive prefixes (exact carry-out)
__device__ int   g_flag[NBLK_];          // epoch-tagged: 2*launch + {1:E, 2:V}
__device__ int   g_ticket;               // monotone across launches (epoch source)

// ---------------------------------------------------------------------------
__global__ void __launch_bounds__(NTHR_, 6)
ema_kernel(const float* __restrict__ x,
           const float* __restrict__ logit_alpha,
           const float* __restrict__ mix_logits,
           float* __restrict__ out) {
    extern __shared__ __half2 sx[];   // [L_][NTHR_] mixed zero-init output stash
    __shared__ int sh_tvid;
    __shared__ int sh_n;              // E-entries on lookback path
    __shared__ int sh_term;           // vid holding V terminator, or -1 => seed
    __shared__ int sh_path[G_];

    const int tid = threadIdx.x;

    // Monotone ticket: launch epoch + scheduling-ordered vid (deadlock-free).
    if (tid == 0) sh_tvid = atomicAdd(&g_ticket, 1);
    __syncthreads();
    const int tvid   = sh_tvid;
    const int launch = tvid / NBLK_;
    const int vid    = tvid % NBLK_;
    const int fbase  = 2 * launch;      // flag values <= fbase are stale
    const int j      = vid / NCHAIN_;   // chunk index along T
    const int chain  = vid % NCHAIN_;   // (b, half)
    const int b      = chain / NH_;
    const int half   = chain % NH_;
    const int c      = half * CH_ + 2 * tid;       // channel pair (c, c+1)
    const int cpair  = half * (CH_ / 2) + tid;     // float2 index within a row

    // ---- per-channel-pair coefficients (scalar compute, packed carry) ----
    u64 ap0, ap1, ap2, bp0, bp1, bp2, aLp0, aLp1, aLp2, mp0, mp1, mp2;
    {
        float a[K_][2], aL[K_][2];
        #pragma unroll
        for (int k = 0; k < K_; k++) {
            #pragma unroll
            for (int h = 0; h < 2; h++) {
                float la = __ldg(logit_alpha + k * C_ + c + h);
                float av = 1.0f / (1.0f + __expf(-la));
                av = fminf(fmaxf(av, EPSV), 1.0f - EPSV);
                a[k][h] = av;
                float p = av;
                #pragma unroll
                for (int s = 0; s < 6; s++) p *= p;   // a^64
                aL[k][h] = p;
            }
        }
        ap0 = pk2(a[0][0], a[0][1]); ap1 = pk2(a[1][0], a[1][1]); ap2 = pk2(a[2][0], a[2][1]);
        bp0 = pk2(1.0f - a[0][0], 1.0f - a[0][1]);
        bp1 = pk2(1.0f - a[1][0], 1.0f - a[1][1]);
        bp2 = pk2(1.0f - a[2][0], 1.0f - a[2][1]);
        aLp0 = pk2(aL[0][0], aL[0][1]); aLp1 = pk2(aL[1][0], aL[1][1]); aLp2 = pk2(aL[2][0], aL[2][1]);

        float m[K_][2];
        #pragma unroll
        for (int h = 0; h < 2; h++) {
            float l0 = __ldg(mix_logits + (c + h) * K_ + 0);
            float l1 = __ldg(mix_logits + (c + h) * K_ + 1);
            float l2 = __ldg(mix_logits + (c + h) * K_ + 2);
            float mx = fmaxf(l0, fmaxf(l1, l2));
            float e0 = __expf(l0 - mx), e1 = __expf(l1 - mx), e2 = __expf(l2 - mx);
            float inv = 1.0f / (e0 + e1 + e2);
            m[0][h] = e0 * inv; m[1][h] = e1 * inv; m[2][h] = e2 * inv;
        }
        mp0 = pk2(m[0][0], m[0][1]); mp1 = pk2(m[1][0], m[1][1]); mp2 = pk2(m[2][0], m[2][1]);
    }

    // Exact seed: y[-1] = x[b,0,c] gives y[0] = x[0].
    u64 xb0p;
    {
        float2 xb = __ldg(reinterpret_cast<const float2*>(x + (size_t)b * T_ * C_) + cpair);
        xb0p = pk2(xb.x, xb.y);
    }

    // ---- phase 1: single HBM read (LDG.64); packed zero-init recurrence;
    //      stash MIXED zero-output in half2 smem; keep end states E ----
    const float2* xp = reinterpret_cast<const float2*>(x)
                     + ((size_t)b * T_ + (size_t)j * L_) * (C_ / 2) + cpair;
    u64 y0 = 0ull, y1 = 0ull, y2 = 0ull;   // packed {0.0f, 0.0f}
    #pragma unroll
    for (int ii = 0; ii < L_; ii += 8) {
        float2 v[8];
        #pragma unroll
        for (int u = 0; u < 8; u++) v[u] = __ldg(xp + (size_t)(ii + u) * (C_ / 2));
        #pragma unroll
        for (int u = 0; u < 8; u++) {
            u64 xv = pk2(v[u].x, v[u].y);
            y0 = fma2_(ap0, y0, mul2_(bp0, xv));
            y1 = fma2_(ap1, y1, mul2_(bp1, xv));
            y2 = fma2_(ap2, y2, mul2_(bp2, xv));
            u64 s = mul2_(mp0, y0);
            s = fma2_(mp1, y1, s);
            s = fma2_(mp2, y2, s);
            float2 sf = up2(s);
            sx[(ii + u) * NTHR_ + tid] = __floats2half2_rn(sf.x, sf.y);
        }
    }

    // ---- publish E (flag = fbase+1) ----
    const size_t ebase = (size_t)vid * (K_ * CH_) + 2 * tid;   // float2-aligned
    {
        float2 e0 = up2(y0), e1 = up2(y1), e2 = up2(y2);
        __stcg(reinterpret_cast<float2*>(g_E + ebase + 0 * CH_), e0);
        __stcg(reinterpret_cast<float2*>(g_E + ebase + 1 * CH_), e1);
        __stcg(reinterpret_cast<float2*>(g_E + ebase + 2 * CH_), e2);
    }
    __threadfence();
    __syncthreads();
    if (tid == 0) atomicExch(&g_flag[vid], fbase + 1);

    // ---- lookback path resolution: tid0 walks flags, records the path ----
    if (tid == 0) {
        int n = 0, term = -1;
        int pv = vid - NCHAIN_;
        while (pv >= 0) {
            int f;
            do {
                f = atomicAdd(&g_flag[pv], 0) - fbase;   // stale => <= 0
                if (f <= 0) __nanosleep(50);
            } while (f <= 0);
            if (f == 2) { term = pv; break; }
            sh_path[n++] = pv;            // f==1: aggregate, keep walking
            pv -= NCHAIN_;
        }
        sh_n = n; sh_term = term;
    }
    __syncthreads();
    __threadfence();   // acquire: order E/V data loads after flag observations

    // ---- all threads: accumulate exact carry along the recorded path ----
    u64 c0, c1, c2;
    {
        const int n = sh_n, term = sh_term;
        u64 acc0 = 0ull, acc1 = 0ull, acc2 = 0ull;
        u64 p0 = pk2(1.0f, 1.0f), p1 = p0, p2 = p0;
        for (int d = 0; d < n; d++) {
            const float* src = g_E + (size_t)sh_path[d] * (K_ * CH_) + 2 * tid;
            float2 e0 = __ldcg(reinterpret_cast<const float2*>(src + 0 * CH_));
            float2 e1 = __ldcg(reinterpret_cast<const float2*>(src + 1 * CH_));
            float2 e2 = __ldcg(reinterpret_cast<const float2*>(src + 2 * CH_));
            acc0 = fma2_(p0, pk2(e0.x, e0.y), acc0);
            acc1 = fma2_(p1, pk2(e1.x, e1.y), acc1);
            acc2 = fma2_(p2, pk2(e2.x, e2.y), acc2);
            p0 = mul2_(p0, aLp0); p1 = mul2_(p1, aLp1); p2 = mul2_(p2, aLp2);
        }
        u64 t0, t1, t2;
        if (term >= 0) {
            const float* src = g_V + (size_t)term * (K_ * CH_) + 2 * tid;
            float2 v0 = __ldcg(reinterpret_cast<const float2*>(src + 0 * CH_));
            float2 v1 = __ldcg(reinterpret_cast<const float2*>(src + 1 * CH_));
            float2 v2 = __ldcg(reinterpret_cast<const float2*>(src + 2 * CH_));
            t0 = pk2(v0.x, v0.y); t1 = pk2(v1.x, v1.y); t2 = pk2(v2.x, v2.y);
        } else {
            t0 = xb0p; t1 = xb0p; t2 = xb0p;   // reached j = -1: exact seed
        }
        c0 = fma2_(p0, t0, acc0);
        c1 = fma2_(p1, t1, acc1);
        c2 = fma2_(p2, t2, acc2);
    }

    // ---- publish inclusive prefix V = aL*carry + E (flag = fbase+2) ----
    {
        float2 v0 = up2(fma2_(aLp0, c0, y0));
        float2 v1 = up2(fma2_(aLp1, c1, y1));
        float2 v2 = up2(fma2_(aLp2, c2, y2));
        __stcg(reinterpret_cast<float2*>(g_V + ebase + 0 * CH_), v0);
        __stcg(reinterpret_cast<float2*>(g_V + ebase + 1 * CH_), v1);
        __stcg(reinterpret_cast<float2*>(g_V + ebase + 2 * CH_), v2);
    }
    __threadfence();
    __syncthreads();
    if (tid == 0) atomicExch(&g_flag[vid], fbase + 2);

    // ---- phase 2: out[i] = s[i] + sum_k (m_k c_k) a_k^(i+1)  (exact identity;
    //      only approximation is one fp16 rounding of the stash) ----
    u64 pc0 = mul2_(mp0, c0), pc1 = mul2_(mp1, c1), pc2 = mul2_(mp2, c2);
    u64 pw0 = ap0, pw1 = ap1, pw2 = ap2;
    float2* op = reinterpret_cast<float2*>(out)
               + ((size_t)b * T_ + (size_t)j * L_) * (C_ / 2) + cpair;
    #pragma unroll 8
    for (int i = 0; i < L_; i++) {
        float2 bf = __half22float2(sx[i * NTHR_ + tid]);
        u64 corr = mul2_(pc0, pw0);
        corr = fma2_(pc1, pw1, corr);
        corr = fma2_(pc2, pw2, corr);
        u64 o = add2_(pk2(bf.x, bf.y), corr);
        op[(size_t)i * (C_ / 2)] = up2(o);
        pw0 = mul2_(pw0, ap0); pw1 = mul2_(pw1, ap1); pw2 = mul2_(pw2, ap2);
    }
}

// ---------------------------------------------------------------------------
extern "C" void kernel_launch(void* const* d_in, const int* in_sizes, int n_in,
                              void* d_out, int out_size) {
    const float* x           = (const float*)d_in[0];
    const float* logit_alpha = (const float*)d_in[1];
    const float* mix_logits  = (const float*)d_in[2];
    float*       out         = (float*)d_out;

    static bool attr_done = false;
    if (!attr_done) {   // host-side attribute only; no allocation, no skipped work
        cudaFuncSetAttribute(ema_kernel,
                             cudaFuncAttributeMaxDynamicSharedMemorySize,
                             (int)SMEM_BYTES);
        attr_done = true;
    }

    ema_kernel<<<NBLK_, NTHR_, SMEM_BYTES>>>(x, logit_alpha, mix_logits, out);
}

// round 11
// speedup vs baseline: 1.3615x; 1.3615x over previous
#include <cuda_runtime.h>
#include <cuda_fp16.h>

#define B_ 16
#define T_ 4096
#define C_ 512
#define K_ 3
#define L_ 64
#define G_ (T_ / L_)          // 64 chunks
#define CH_ 256               // channels per block (thread = channel)
#define NH_ (C_ / CH_)        // 2 halves
#define NCHAIN_ (B_ * NH_)    // 32 independent carry chains
#define NBLK_ (G_ * NCHAIN_)  // 2048 blocks
#define EPSV 1e-4f

// Lookback scratch (no allocations allowed -> __device__ globals, zero-init).
__device__ float g_E[NBLK_ * K_ * CH_];   // chunk-local end states (zero-init recurrence)
__device__ float g_V[NBLK_ * K_ * CH_];   // inclusive prefixes (exact carry-out)
__device__ int   g_flag[NBLK_];           // epoch-tagged: 2*launch + {1:E, 2:V}
__device__ int   g_ticket;                // monotone across launches (epoch source)

// ---------------------------------------------------------------------------
__global__ void __launch_bounds__(CH_, 5)
ema_kernel(const float* __restrict__ x,
           const float* __restrict__ logit_alpha,
           const float* __restrict__ mix_logits,
           float* __restrict__ out) {
    __shared__ __half sx[L_ * CH_];   // mixed zero-init output stash (32 KB)
    __shared__ int sh_tvid;
    __shared__ int sh_n;              // E-entries on lookback path
    __shared__ int sh_term;           // vid holding V terminator, or -1 => seed

    const int tid = threadIdx.x;

    // Monotone ticket: encodes launch epoch and scheduling-ordered vid.
    if (tid == 0) sh_tvid = atomicAdd(&g_ticket, 1);
    __syncthreads();
    const int tvid   = sh_tvid;
    const int launch = tvid / NBLK_;
    const int vid    = tvid % NBLK_;
    const int fbase  = 2 * launch;     // flag values <= fbase are stale
    const int j      = vid / NCHAIN_;  // chunk index along T
    const int chain  = vid % NCHAIN_;  // (b, half)
    const int b      = chain / NH_;
    const int half   = chain % NH_;
    const int c      = half * CH_ + tid;

    // ---- per-channel coefficients ----
    float a0, a1, a2, b0, b1, b2, aL0, aL1, aL2;
    {
        float la0 = __ldg(logit_alpha + 0 * C_ + c);
        float la1 = __ldg(logit_alpha + 1 * C_ + c);
        float la2 = __ldg(logit_alpha + 2 * C_ + c);
        a0 = 1.0f / (1.0f + __expf(-la0));
        a1 = 1.0f / (1.0f + __expf(-la1));
        a2 = 1.0f / (1.0f + __expf(-la2));
        a0 = fminf(fmaxf(a0, EPSV), 1.0f - EPSV);
        a1 = fminf(fmaxf(a1, EPSV), 1.0f - EPSV);
        a2 = fminf(fmaxf(a2, EPSV), 1.0f - EPSV);
        b0 = 1.0f - a0; b1 = 1.0f - a1; b2 = 1.0f - a2;
        aL0 = a0; aL1 = a1; aL2 = a2;
        #pragma unroll
        for (int s = 0; s < 6; s++) { aL0 *= aL0; aL1 *= aL1; aL2 *= aL2; }  // a^64
    }
    float m0, m1, m2;
    {
        float l0 = __ldg(mix_logits + c * K_ + 0);
        float l1 = __ldg(mix_logits + c * K_ + 1);
        float l2 = __ldg(mix_logits + c * K_ + 2);
        float mx = fmaxf(l0, fmaxf(l1, l2));
        float e0 = __expf(l0 - mx), e1 = __expf(l1 - mx), e2 = __expf(l2 - mx);
        float inv = 1.0f / (e0 + e1 + e2);
        m0 = e0 * inv; m1 = e1 * inv; m2 = e2 * inv;
    }

    // Exact seed: y[-1] = x[b,0,c] makes y[0] = x[0].
    const float xb0 = __ldg(x + (size_t)b * T_ * C_ + c);

    // ---- phase 1: single HBM read of x tile; zero-init recurrence;
    //      stash MIXED zero-output in fp16 smem; keep end states E ----
    const float* xp = x + ((size_t)b * T_ + (size_t)j * L_) * C_ + c;
    float y0 = 0.0f, y1 = 0.0f, y2 = 0.0f;
    #pragma unroll
    for (int ii = 0; ii < L_; ii += 8) {
        float v[8];
        #pragma unroll
        for (int u = 0; u < 8; u++) v[u] = __ldg(xp + (size_t)(ii + u) * C_);
        #pragma unroll
        for (int u = 0; u < 8; u++) {
            y0 = fmaf(a0, y0, b0 * v[u]);
            y1 = fmaf(a1, y1, b1 * v[u]);
            y2 = fmaf(a2, y2, b2 * v[u]);
            sx[(ii + u) * CH_ + tid] =
                __float2half(fmaf(m2, y2, fmaf(m1, y1, m0 * y0)));
        }
    }

    // ---- publish E (flag = fbase+1) ----
    const int ebase = vid * (K_ * CH_) + tid;
    __stcg(&g_E[ebase + 0 * CH_], y0);
    __stcg(&g_E[ebase + 1 * CH_], y1);
    __stcg(&g_E[ebase + 2 * CH_], y2);
    __threadfence();
    __syncthreads();
    if (tid == 0) atomicExch(&g_flag[vid], fbase + 1);

    // ---- PARALLEL lookback poll (warp 0): depth d's predecessor is
    //      vid-(d+1)*NCHAIN_ for d<j; depth j is the seed (always a terminator).
    //      Lane l watches depths l and l+32; two ballots build 64-bit masks.
    //      Exit when the nearest terminator t has all shallower E's ready. ----
    if (tid < 32) {
        const int lane = tid;
        const int d0 = lane, d1 = lane + 32;
        int f0c = 0, f1c = 0;                 // cached flag states (d < j only)
        for (;;) {
            int s0, s1;
            if (d0 > j)       s0 = 3;
            else if (d0 == j) s0 = 2;
            else {
                if (f0c < 2) f0c = __ldcg(&g_flag[vid - (d0 + 1) * NCHAIN_]) - fbase;
                s0 = f0c;
            }
            if (d1 > j)       s1 = 3;
            else if (d1 == j) s1 = 2;
            else {
                if (f1c < 2) f1c = __ldcg(&g_flag[vid - (d1 + 1) * NCHAIN_]) - fbase;
                s1 = f1c;
            }
            unsigned b1lo = __ballot_sync(0xffffffffu, s0 >= 1);
            unsigned b2lo = __ballot_sync(0xffffffffu, s0 >= 2);
            unsigned b1hi = __ballot_sync(0xffffffffu, s1 >= 1);
            unsigned b2hi = __ballot_sync(0xffffffffu, s1 >= 2);
            unsigned long long m1m = (unsigned long long)b1lo | ((unsigned long long)b1hi << 32);
            unsigned long long m2m = (unsigned long long)b2lo | ((unsigned long long)b2hi << 32);
            int t = __ffsll((long long)m2m) - 1;          // nearest terminator (<= j)
            unsigned long long need = (t == 0) ? 0ull : ((1ull << t) - 1ull);
            if ((m1m & need) == need) {
                if (lane == 0) {
                    sh_n    = t;
                    sh_term = (t == j) ? -1 : vid - (t + 1) * NCHAIN_;
                }
                break;
            }
            __nanosleep(60);
        }
    }
    __syncthreads();
    __threadfence();   // acquire: order E/V data loads after flag observations

    // ---- all threads: Horner aggregation from terminator toward chunk j-1 ----
    float c0, c1, c2;
    {
        const int n = sh_n, term = sh_term;
        if (term >= 0) {
            const float* src = g_V + (size_t)term * (K_ * CH_) + tid;
            c0 = __ldcg(src + 0 * CH_);
            c1 = __ldcg(src + 1 * CH_);
            c2 = __ldcg(src + 2 * CH_);
        } else {
            c0 = xb0; c1 = xb0; c2 = xb0;   // seed (depth j): exact y[-1]
        }
        #pragma unroll 2
        for (int d = n - 1; d >= 0; d--) {
            const float* src = g_E + (size_t)(vid - (d + 1) * NCHAIN_) * (K_ * CH_) + tid;
            c0 = fmaf(aL0, c0, __ldcg(src + 0 * CH_));
            c1 = fmaf(aL1, c1, __ldcg(src + 1 * CH_));
            c2 = fmaf(aL2, c2, __ldcg(src + 2 * CH_));
        }
    }

    // ---- publish inclusive prefix V = aL*carry + E (flag = fbase+2) ----
    __stcg(&g_V[ebase + 0 * CH_], fmaf(aL0, c0, y0));
    __stcg(&g_V[ebase + 1 * CH_], fmaf(aL1, c1, y1));
    __stcg(&g_V[ebase + 2 * CH_], fmaf(aL2, c2, y2));
    __threadfence();
    __syncthreads();
    if (tid == 0) atomicExch(&g_flag[vid], fbase + 2);

    // ---- phase 2: out[i] = s[i] + sum_k (m_k c_k) a_k^(i+1)  (exact identity;
    //      only approximation is one fp16 rounding of the stash) ----
    float pc0 = m0 * c0, pc1 = m1 * c1, pc2 = m2 * c2;
    float pw0 = a0, pw1 = a1, pw2 = a2;
    float* op = out + ((size_t)b * T_ + (size_t)j * L_) * C_ + c;
    #pragma unroll 8
    for (int i = 0; i < L_; i++) {
        float base = __half2float(sx[i * CH_ + tid]);
        float corr = fmaf(pc2, pw2, fmaf(pc1, pw1, pc0 * pw0));
        op[(size_t)i * C_] = base + corr;
        pw0 *= a0; pw1 *= a1; pw2 *= a2;
    }
}

// ---------------------------------------------------------------------------
extern "C" void kernel_launch(void* const* d_in, const int* in_sizes, int n_in,
                              void* d_out, int out_size) {
    const float* x           = (const float*)d_in[0];
    const float* logit_alpha = (const float*)d_in[1];
    const float* mix_logits  = (const float*)d_in[2];
    float*       out         = (float*)d_out;

    ema_kernel<<<NBLK_, CH_>>>(x, logit_alpha, mix_logits, out);
}